// round 3
// baseline (speedup 1.0000x reference)
#include <cuda_runtime.h>

#define M_     32
#define N_     2048
#define D_     128
#define L_     32768
#define H_     16
#define QKV3_  6144
#define CHUNK_ 1024
#define NC_    32          // L_/CHUNK_
#define KB_    128         // keys per subtile
#define NSUB_  8           // CHUNK_/KB_

// ---------------- device scratch (no allocation allowed) ----------------
__device__ float g_scale[M_];
__device__ float g_qkv[M_ * QKV3_];
__device__ float g_num[H_ * NC_ * M_ * D_];   // 8 MB partial numerators
__device__ float g_den[H_ * NC_ * M_];        // partial denominators

typedef unsigned long long u64;

// ---------------- packed f32x2 helpers (sm_103a) ----------------
__device__ __forceinline__ u64 ffma2(u64 a, u64 b, u64 c) {
    u64 d;
    asm("fma.rn.f32x2 %0, %1, %2, %3;" : "=l"(d) : "l"(a), "l"(b), "l"(c));
    return d;
}
__device__ __forceinline__ u64 pack2(float lo, float hi) {
    u64 r;
    asm("mov.b64 %0, {%1, %2};" : "=l"(r) : "f"(lo), "f"(hi));
    return r;
}
__device__ __forceinline__ u64 dup2(float x) { return pack2(x, x); }
__device__ __forceinline__ void unpack2(u64 v, float& lo, float& hi) {
    asm("mov.b64 {%0, %1}, %2;" : "=f"(lo), "=f"(hi) : "l"(v));
}

// ---------------- kernel 1: RMSNorm row scales ----------------
__global__ void rms_kernel(const float* __restrict__ X) {
    int m = blockIdx.x;
    float s = 0.f;
    for (int k = threadIdx.x; k < N_; k += 256) {
        float v = X[m * N_ + k];
        s += v * v;
    }
    __shared__ float red[256];
    red[threadIdx.x] = s;
    __syncthreads();
    for (int o = 128; o > 0; o >>= 1) {
        if (threadIdx.x < o) red[threadIdx.x] += red[threadIdx.x + o];
        __syncthreads();
    }
    if (threadIdx.x == 0) g_scale[m] = rsqrtf(red[0] * (1.0f / N_));
}

// ---------------- kernel 2a: zero qkv (atomics target) ----------------
__global__ void zero_qkv() {
    int i = blockIdx.x * 256 + threadIdx.x;
    if (i < M_ * QKV3_) g_qkv[i] = 0.f;
}

// ---------------- kernel 2b: QKV GEMM (8m x 2n per thread) ----------------
#define BN2_     128
#define KC2_     32
#define KSPLIT2_ 8
#define KSLAB2_  (N_ / KSPLIT2_)   // 256
#define XS_S     36

__global__ __launch_bounds__(256) void qkv_gemm(const float* __restrict__ X,
                                                const float* __restrict__ W) {
    __shared__ float Xs[KC2_ * XS_S];     // [kk][m] transposed, scaled
    __shared__ float Ws[KC2_ * BN2_];     // [kk][col]
    const int t  = threadIdx.x;
    const int mg = t >> 6;    // 0..3  -> rows mg*8 .. +8
    const int ng = t & 63;    // 0..63 -> cols 2ng, 2ng+1
    const int colBase = blockIdx.x * BN2_;
    const int kBase0  = blockIdx.y * KSLAB2_;

    u64 acc[4][2];
#pragma unroll
    for (int i = 0; i < 4; i++) { acc[i][0] = 0ull; acc[i][1] = 0ull; }

    for (int kc = 0; kc < KSLAB2_; kc += KC2_) {
        const int kb = kBase0 + kc;
        __syncthreads();
        // X chunk [32m x 32k], read coalesced, store transposed+scaled
#pragma unroll
        for (int i = 0; i < 4; i++) {
            int idx = t + i * 256;           // 0..1023
            int m   = idx >> 5;
            int kk  = idx & 31;
            Xs[kk * XS_S + m] = X[m * N_ + kb + kk] * g_scale[m];
        }
        // W chunk [32k x 128cols] as float4
#pragma unroll
        for (int i = 0; i < 4; i++) {
            int idx = t + i * 256;           // 0..1023
            int kk  = idx >> 5;
            int c4  = idx & 31;
            *(float4*)&Ws[kk * BN2_ + 4 * c4] =
                *(const float4*)&W[(size_t)(kb + kk) * QKV3_ + colBase + 4 * c4];
        }
        __syncthreads();
#pragma unroll 4
        for (int kk = 0; kk < KC2_; kk++) {
            float4 xa = *(const float4*)&Xs[kk * XS_S + mg * 8];
            float4 xb = *(const float4*)&Xs[kk * XS_S + mg * 8 + 4];
            u64 x01 = pack2(xa.x, xa.y), x23 = pack2(xa.z, xa.w);
            u64 x45 = pack2(xb.x, xb.y), x67 = pack2(xb.z, xb.w);
            u64 wv = *(const u64*)&Ws[kk * BN2_ + 2 * ng];
            float w0, w1; unpack2(wv, w0, w1);
            u64 wd0 = dup2(w0), wd1 = dup2(w1);
            acc[0][0] = ffma2(x01, wd0, acc[0][0]);
            acc[1][0] = ffma2(x23, wd0, acc[1][0]);
            acc[2][0] = ffma2(x45, wd0, acc[2][0]);
            acc[3][0] = ffma2(x67, wd0, acc[3][0]);
            acc[0][1] = ffma2(x01, wd1, acc[0][1]);
            acc[1][1] = ffma2(x23, wd1, acc[1][1]);
            acc[2][1] = ffma2(x45, wd1, acc[2][1]);
            acc[3][1] = ffma2(x67, wd1, acc[3][1]);
        }
    }
#pragma unroll
    for (int i = 0; i < 4; i++) {
#pragma unroll
        for (int j = 0; j < 2; j++) {
            float a, b;
            unpack2(acc[i][j], a, b);
            int m0  = mg * 8 + 2 * i;
            int col = colBase + 2 * ng + j;
            atomicAdd(&g_qkv[m0 * QKV3_ + col], a);
            atomicAdd(&g_qkv[(m0 + 1) * QKV3_ + col], b);
        }
    }
}

// ---------------- kernel 3: split-KV attention partials ----------------
// smem (floats):
//   Qt  [128 d][36]  (q transposed)          @ 0       4608
//   Et  [128 l][36]  (exp(scores) transposed) @ 4608    4608
//   den [32]                                  @ 9216
//   KV union:                                 @ 9248
//     Kt [128 d][130] (keys transposed)       16640
//     Vs [128 l][128] (natural)               16384
#define QT_S     36
#define ET_S     36
#define ET_OFF   4608
#define DEN_OFF  9216
#define KV_OFF   9248
#define KT_S     130
#define SMEM_FLOATS (KV_OFF + D_ * KT_S)      // 25888
#define SMEM_BYTES  (SMEM_FLOATS * 4)         // 103552

__global__ __launch_bounds__(256, 2) void attn_partial(
    const float* __restrict__ cK,
    const float* __restrict__ cV,
    const int* __restrict__ Pp)
{
    extern __shared__ float sm[];
    float* Qt  = sm;
    float* Et  = sm + ET_OFF;
    float* den = sm + DEN_OFF;
    float* KV  = sm + KV_OFF;

    const int h = blockIdx.y;
    const int c = blockIdx.x;
    const int P = *Pp;
    const int t  = threadIdx.x;
    const int qg = t >> 6;        // 0..3  -> queries qg*8 .. +8
    const int kg = t & 63;        // 0..63 -> key/d pair 2kg, 2kg+1

    // stage Q transposed for this head
#pragma unroll
    for (int i = 0; i < 16; i++) {
        int idx = t + i * 256;    // 0..4095
        int m = idx >> 7;
        int d = idx & 127;
        Qt[d * QT_S + m] = g_qkv[m * QKV3_ + h * D_ + d];
    }
    if (t < 32) den[t] = 0.f;

    u64 accB[4][2];
#pragma unroll
    for (int i = 0; i < 4; i++) { accB[i][0] = 0ull; accB[i][1] = 0ull; }
    float dreg[8];
#pragma unroll
    for (int i = 0; i < 8; i++) dreg[i] = 0.f;

    const float* Kbase = cK + (size_t)h * L_ * D_;
    const float* Vbase = cV + (size_t)h * L_ * D_;

    for (int sub = 0; sub < NSUB_; sub++) {
        const int l0 = c * CHUNK_ + sub * KB_;

        // ---- stage K transposed (l-in-warp -> conflict-free STS) ----
        __syncthreads();
#pragma unroll
        for (int i = 0; i < 16; i++) {
            int idx = t + i * 256;       // float4 index 0..4095
            int l  = idx & 127;
            int d4 = idx >> 7;           // 0..31
            int gl = l0 + l;
            float4 k4;
            if (gl >= P && gl < P + M_)
                k4 = *(const float4*)&g_qkv[(gl - P) * QKV3_ + N_ + h * D_ + 4 * d4];
            else
                k4 = *(const float4*)&Kbase[(size_t)gl * D_ + 4 * d4];
            KV[(4 * d4 + 0) * KT_S + l] = k4.x;
            KV[(4 * d4 + 1) * KT_S + l] = k4.y;
            KV[(4 * d4 + 2) * KT_S + l] = k4.z;
            KV[(4 * d4 + 3) * KT_S + l] = k4.w;
        }
        __syncthreads();

        // ---- phase A: scores (8q x 2k per thread) ----
        u64 accA[4][2];
#pragma unroll
        for (int i = 0; i < 4; i++) { accA[i][0] = 0ull; accA[i][1] = 0ull; }
#pragma unroll 2
        for (int d = 0; d < D_; d++) {
            float4 qa = *(const float4*)&Qt[d * QT_S + qg * 8];       // broadcast
            float4 qb = *(const float4*)&Qt[d * QT_S + qg * 8 + 4];   // broadcast
            u64 q01 = pack2(qa.x, qa.y), q23 = pack2(qa.z, qa.w);
            u64 q45 = pack2(qb.x, qb.y), q67 = pack2(qb.z, qb.w);
            u64 kk = *(const u64*)&KV[d * KT_S + 2 * kg];
            float k0, k1; unpack2(kk, k0, k1);
            u64 kd0 = dup2(k0), kd1 = dup2(k1);
            accA[0][0] = ffma2(q01, kd0, accA[0][0]);
            accA[1][0] = ffma2(q23, kd0, accA[1][0]);
            accA[2][0] = ffma2(q45, kd0, accA[2][0]);
            accA[3][0] = ffma2(q67, kd0, accA[3][0]);
            accA[0][1] = ffma2(q01, kd1, accA[0][1]);
            accA[1][1] = ffma2(q23, kd1, accA[1][1]);
            accA[2][1] = ffma2(q45, kd1, accA[2][1]);
            accA[3][1] = ffma2(q67, kd1, accA[3][1]);
        }
        // exp -> Et (transposed), accumulate denominators in regs
#pragma unroll
        for (int lp = 0; lp < 2; lp++) {
            float e[8];
#pragma unroll
            for (int i = 0; i < 4; i++) {
                float a, b; unpack2(accA[i][lp], a, b);
                e[2 * i]     = __expf(a);
                e[2 * i + 1] = __expf(b);
                dreg[2 * i]     += e[2 * i];
                dreg[2 * i + 1] += e[2 * i + 1];
            }
            float4 ea = make_float4(e[0], e[1], e[2], e[3]);
            float4 eb = make_float4(e[4], e[5], e[6], e[7]);
            *(float4*)&Et[(2 * kg + lp) * ET_S + qg * 8]     = ea;
            *(float4*)&Et[(2 * kg + lp) * ET_S + qg * 8 + 4] = eb;
        }
        __syncthreads();

        // ---- stage V (natural layout, coalesced) ----
#pragma unroll
        for (int i = 0; i < 16; i++) {
            int idx = t + i * 256;       // float4 index
            int l  = idx >> 5;           // 0..127
            int d4 = idx & 31;
            int gl = l0 + l;
            float4 v4;
            if (gl >= P && gl < P + M_)
                v4 = *(const float4*)&g_qkv[(gl - P) * QKV3_ + 2 * N_ + h * D_ + 4 * d4];
            else
                v4 = *(const float4*)&Vbase[(size_t)gl * D_ + 4 * d4];
            *(float4*)&KV[l * D_ + 4 * d4] = v4;
        }
        __syncthreads();

        // ---- phase B: out += E @ V (8q x 2d per thread) ----
#pragma unroll 2
        for (int l = 0; l < KB_; l++) {
            float4 ea = *(const float4*)&Et[l * ET_S + qg * 8];       // broadcast
            float4 eb = *(const float4*)&Et[l * ET_S + qg * 8 + 4];   // broadcast
            u64 e01 = pack2(ea.x, ea.y), e23 = pack2(ea.z, ea.w);
            u64 e45 = pack2(eb.x, eb.y), e67 = pack2(eb.z, eb.w);
            u64 vv = *(const u64*)&KV[l * D_ + 2 * kg];
            float v0, v1; unpack2(vv, v0, v1);
            u64 vd0 = dup2(v0), vd1 = dup2(v1);
            accB[0][0] = ffma2(e01, vd0, accB[0][0]);
            accB[1][0] = ffma2(e23, vd0, accB[1][0]);
            accB[2][0] = ffma2(e45, vd0, accB[2][0]);
            accB[3][0] = ffma2(e67, vd0, accB[3][0]);
            accB[0][1] = ffma2(e01, vd1, accB[0][1]);
            accB[1][1] = ffma2(e23, vd1, accB[1][1]);
            accB[2][1] = ffma2(e45, vd1, accB[2][1]);
            accB[3][1] = ffma2(e67, vd1, accB[3][1]);
        }
    }

    // ---- epilogue ----
#pragma unroll
    for (int i = 0; i < 8; i++) atomicAdd(&den[qg * 8 + i], dreg[i]);

    const size_t nbase = (size_t)(h * NC_ + c) * M_ * D_;
#pragma unroll
    for (int i = 0; i < 4; i++) {
        float a0, b0, a1, b1;
        unpack2(accB[i][0], a0, b0);   // d = 2kg
        unpack2(accB[i][1], a1, b1);   // d = 2kg+1
        int q0 = qg * 8 + 2 * i;
        *(u64*)&g_num[nbase + (size_t)q0 * D_ + 2 * kg]       = pack2(a0, a1);
        *(u64*)&g_num[nbase + (size_t)(q0 + 1) * D_ + 2 * kg] = pack2(b0, b1);
    }
    __syncthreads();
    if (t < 32) g_den[(h * NC_ + c) * M_ + t] = den[t];
}

// ---------------- kernel 4: deterministic reduce + output ----------------
__global__ void reduce_out(float* __restrict__ out) {
    int hm = blockIdx.x;          // 0..511
    int h = hm >> 5;
    int m = hm & 31;
    int d = threadIdx.x;          // 0..127
    float dsum = 0.f;
#pragma unroll 8
    for (int c = 0; c < NC_; c++)
        dsum += g_den[(h * NC_ + c) * M_ + m];
    float nsum = 0.f;
#pragma unroll 8
    for (int c = 0; c < NC_; c++)
        nsum += g_num[((size_t)(h * NC_ + c) * M_ + m) * D_ + d];
    out[m * N_ + h * D_ + d] = nsum / dsum;
}

// ---------------- launch ----------------
extern "C" void kernel_launch(void* const* d_in, const int* in_sizes, int n_in,
                              void* d_out, int out_size) {
    const float* X  = (const float*)d_in[0];
    const float* W  = (const float*)d_in[1];
    const float* cK = (const float*)d_in[2];
    const float* cV = (const float*)d_in[3];
    const int*   P  = (const int*)d_in[4];
    float* out = (float*)d_out;

    cudaFuncSetAttribute(attn_partial,
                         cudaFuncAttributeMaxDynamicSharedMemorySize, SMEM_BYTES);

    rms_kernel<<<M_, 256>>>(X);
    zero_qkv<<<(M_ * QKV3_ + 255) / 256, 256>>>();
    qkv_gemm<<<dim3(QKV3_ / BN2_, KSPLIT2_), 256>>>(X, W);
    attn_partial<<<dim3(NC_, H_), 256, SMEM_BYTES>>>(cK, cV, P);
    reduce_out<<<H_ * M_, 128>>>(out);
}

// round 8
// speedup vs baseline: 1.7931x; 1.7931x over previous
#include <cuda_runtime.h>
#include <cstdint>

#define M_     32
#define N_     2048
#define D_     128
#define L_     32768
#define H_     16
#define QKV3_  6144
#define CHUNK_ 1024
#define NC_    32
#define SK_    64          // keys per subtile
#define NSUB_  16          // CHUNK_/SK_

typedef unsigned long long u64;
typedef unsigned int u32;

__device__ float g_scale[M_];
__device__ float g_qkv[M_ * QKV3_];
__device__ float g_num[H_ * NC_ * M_ * D_];   // [hc][q][d]
__device__ float g_den[H_ * NC_ * M_];

// ---- helpers ----
__device__ __forceinline__ u64 ffma2(u64 a, u64 b, u64 c) {
    u64 d; asm("fma.rn.f32x2 %0, %1, %2, %3;" : "=l"(d) : "l"(a), "l"(b), "l"(c)); return d;
}
__device__ __forceinline__ u64 pack2(float lo, float hi) {
    u64 r; asm("mov.b64 %0, {%1, %2};" : "=l"(r) : "f"(lo), "f"(hi)); return r;
}
__device__ __forceinline__ u64 dup2(float x) { return pack2(x, x); }
__device__ __forceinline__ void unpack2(u64 v, float& lo, float& hi) {
    asm("mov.b64 {%0, %1}, %2;" : "=f"(lo), "=f"(hi) : "l"(v));
}
__device__ __forceinline__ float tf32r(float x) {
    float r; asm("cvt.rna.tf32.f32 %0, %1;" : "=f"(r) : "f"(x)); return r;
}
__device__ __forceinline__ u32 cvta_smem(const void* p) {
    u32 a; asm("{ .reg .u64 t; cvta.to.shared.u64 t, %1; cvt.u32.u64 %0, t; }" : "=r"(a) : "l"(p)); return a;
}
__device__ __forceinline__ void cpasync16(u32 s, const void* g) {
    asm volatile("cp.async.cg.shared.global [%0], [%1], 16;" :: "r"(s), "l"(g));
}
#define CP_COMMIT() asm volatile("cp.async.commit_group;" ::: "memory")
#define CP_WAIT0()  asm volatile("cp.async.wait_group 0;" ::: "memory")
#define CP_WAIT1()  asm volatile("cp.async.wait_group 1;" ::: "memory")

// mma.sync m16n8k8 tf32 (legacy HMMA path, base ISA)
__device__ __forceinline__ void mma8(float* c, float a0, float a1, float a2, float a3,
                                     float b0, float b1) {
    asm volatile("mma.sync.aligned.m16n8k8.row.col.f32.tf32.tf32.f32 "
        "{%0,%1,%2,%3}, {%4,%5,%6,%7}, {%8,%9}, {%0,%1,%2,%3};"
        : "+f"(c[0]), "+f"(c[1]), "+f"(c[2]), "+f"(c[3])
        : "r"(__float_as_uint(a0)), "r"(__float_as_uint(a1)),
          "r"(__float_as_uint(a2)), "r"(__float_as_uint(a3)),
          "r"(__float_as_uint(b0)), "r"(__float_as_uint(b1)));
}

// ---- kernel 1: RMS scales ----
__global__ void rms_kernel(const float* __restrict__ X) {
    int m = blockIdx.x;
    float s = 0.f;
    for (int k = threadIdx.x; k < N_; k += 256) { float v = X[m * N_ + k]; s += v * v; }
    __shared__ float red[256];
    red[threadIdx.x] = s; __syncthreads();
    for (int o = 128; o > 0; o >>= 1) {
        if (threadIdx.x < o) red[threadIdx.x] += red[threadIdx.x + o];
        __syncthreads();
    }
    if (threadIdx.x == 0) g_scale[m] = rsqrtf(red[0] * (1.0f / N_));
}

__global__ void zero_qkv() {
    int i = blockIdx.x * 256 + threadIdx.x;
    if (i < M_ * QKV3_) g_qkv[i] = 0.f;
}

// ---- kernel 2: QKV GEMM (scalar f32x2, 8m x 2n) ----
#define BN2_     128
#define KC2_     32
#define KSPLIT2_ 8
#define KSLAB2_  (N_ / KSPLIT2_)
#define XS_S     36
__global__ __launch_bounds__(256) void qkv_gemm(const float* __restrict__ X,
                                                const float* __restrict__ W) {
    __shared__ float Xs[KC2_ * XS_S];
    __shared__ float Ws[KC2_ * BN2_];
    const int t = threadIdx.x, mg = t >> 6, ng = t & 63;
    const int colBase = blockIdx.x * BN2_, kBase0 = blockIdx.y * KSLAB2_;
    u64 acc[4][2];
#pragma unroll
    for (int i = 0; i < 4; i++) { acc[i][0] = 0ull; acc[i][1] = 0ull; }
    for (int kc = 0; kc < KSLAB2_; kc += KC2_) {
        const int kb = kBase0 + kc;
        __syncthreads();
#pragma unroll
        for (int i = 0; i < 4; i++) {
            int idx = t + i * 256, m = idx >> 5, kk = idx & 31;
            Xs[kk * XS_S + m] = X[m * N_ + kb + kk] * g_scale[m];
        }
#pragma unroll
        for (int i = 0; i < 4; i++) {
            int idx = t + i * 256, kk = idx >> 5, c4 = idx & 31;
            *(float4*)&Ws[kk * BN2_ + 4 * c4] =
                *(const float4*)&W[(size_t)(kb + kk) * QKV3_ + colBase + 4 * c4];
        }
        __syncthreads();
#pragma unroll 4
        for (int kk = 0; kk < KC2_; kk++) {
            float4 xa = *(const float4*)&Xs[kk * XS_S + mg * 8];
            float4 xb = *(const float4*)&Xs[kk * XS_S + mg * 8 + 4];
            u64 x01 = pack2(xa.x, xa.y), x23 = pack2(xa.z, xa.w);
            u64 x45 = pack2(xb.x, xb.y), x67 = pack2(xb.z, xb.w);
            u64 wv = *(const u64*)&Ws[kk * BN2_ + 2 * ng];
            float w0, w1; unpack2(wv, w0, w1);
            u64 wd0 = dup2(w0), wd1 = dup2(w1);
            acc[0][0] = ffma2(x01, wd0, acc[0][0]); acc[1][0] = ffma2(x23, wd0, acc[1][0]);
            acc[2][0] = ffma2(x45, wd0, acc[2][0]); acc[3][0] = ffma2(x67, wd0, acc[3][0]);
            acc[0][1] = ffma2(x01, wd1, acc[0][1]); acc[1][1] = ffma2(x23, wd1, acc[1][1]);
            acc[2][1] = ffma2(x45, wd1, acc[2][1]); acc[3][1] = ffma2(x67, wd1, acc[3][1]);
        }
    }
#pragma unroll
    for (int i = 0; i < 4; i++)
#pragma unroll
        for (int j = 0; j < 2; j++) {
            float a, b; unpack2(acc[i][j], a, b);
            int m0 = mg * 8 + 2 * i, col = colBase + 2 * ng + j;
            atomicAdd(&g_qkv[m0 * QKV3_ + col], a);
            atomicAdd(&g_qkv[(m0 + 1) * QKV3_ + col], b);
        }
}

// ---- kernel 3: mma.sync tf32 attention ----
// smem float offsets
#define KRAW 0                         // [64][132]
#define VRAW 8448                      // [64][132]
#define QT   16896                     // [128 d][36]  raw Q transposed
#define ES   21504                     // [32 q][68]   rounded exp(scores)
#define DEN  23680                     // [32]
#define SMF  23712
#define SMEMB (SMF * 4)                // 94848 B

__global__ __launch_bounds__(256, 2) void attn_mma(
    const float* __restrict__ cK, const float* __restrict__ cV,
    const int* __restrict__ Pp)
{
    extern __shared__ float smf[];
    const u32 sb = cvta_smem(smf);
    const int t = threadIdx.x, w = t >> 5, lane = t & 31;
    const int gid = lane >> 2, tig = lane & 3;
    const int h = blockIdx.y, c = blockIdx.x, P = *Pp;
    const int kg = w >> 1, qh = w & 1;        // QK: key-group / query-half
    const int kb = kg * 16, qb = qh * 16;

    const float* Kh = cK + (size_t)h * L_ * D_;
    const float* Vh = cV + (size_t)h * L_ * D_;

    // stage Q transposed (raw fp32)
#pragma unroll
    for (int i = 0; i < 16; i++) {
        int idx = t + i * 256;           // 0..4095
        int q = idx >> 7, d = idx & 127;
        smf[QT + d * 36 + q] = g_qkv[q * QKV3_ + h * D_ + d];
    }
    if (t < 32) smf[DEN + t] = 0.f;

    float o[2][2][4];                     // PV accumulators [mtile][nblk][frag]
#pragma unroll
    for (int a = 0; a < 2; a++)
#pragma unroll
        for (int b = 0; b < 2; b++)
#pragma unroll
            for (int k = 0; k < 4; k++) o[a][b][k] = 0.f;

    // prologue: async-stage K(0)
    {
        int l0 = c * CHUNK_;
#pragma unroll
        for (int i = 0; i < 8; i++) {
            int idx = t + i * 256, row = idx >> 5, c4 = idx & 31;
            cpasync16(sb + (KRAW + row * 132 + 4 * c4) * 4,
                      &Kh[(size_t)(l0 + row) * D_ + 4 * c4]);
        }
        CP_COMMIT();
    }

    for (int s = 0; s < NSUB_; s++) {
        const int l0 = c * CHUNK_ + s * SK_;
        // stage V(s) async
#pragma unroll
        for (int i = 0; i < 8; i++) {
            int idx = t + i * 256, row = idx >> 5, c4 = idx & 31;
            cpasync16(sb + (VRAW + row * 132 + 4 * c4) * 4,
                      &Vh[(size_t)(l0 + row) * D_ + 4 * c4]);
        }
        CP_COMMIT();
        CP_WAIT1();                       // K(s) ready
        __syncthreads();

        // overwrite fresh K rows
        {
            int lo_ = l0 > P ? l0 : P;
            int hi_ = (l0 + SK_) < (P + M_) ? (l0 + SK_) : (P + M_);
            if (lo_ < hi_) {
                for (int idx = t; idx < (hi_ - lo_) * 32; idx += 256) {
                    int r = idx >> 5, c4 = idx & 31;
                    int gl = lo_ + r;
                    *(float4*)&smf[KRAW + (gl - l0) * 132 + 4 * c4] =
                        *(const float4*)&g_qkv[(gl - P) * QKV3_ + N_ + h * D_ + 4 * c4];
                }
                __syncthreads();
            }
        }

        // ---- QK scores: 3-pass hi/lo tf32 ----
        float sc[2][4];
#pragma unroll
        for (int j = 0; j < 2; j++)
#pragma unroll
            for (int k = 0; k < 4; k++) sc[j][k] = 0.f;
#pragma unroll 4
        for (int ks = 0; ks < 16; ks++) {
            int d0 = ks * 8;
            float kr0 = smf[KRAW + (kb + gid) * 132 + d0 + tig];
            float kr1 = smf[KRAW + (kb + gid + 8) * 132 + d0 + tig];
            float kr2 = smf[KRAW + (kb + gid) * 132 + d0 + tig + 4];
            float kr3 = smf[KRAW + (kb + gid + 8) * 132 + d0 + tig + 4];
            float ah0 = tf32r(kr0), al0 = tf32r(kr0 - ah0);
            float ah1 = tf32r(kr1), al1 = tf32r(kr1 - ah1);
            float ah2 = tf32r(kr2), al2 = tf32r(kr2 - ah2);
            float ah3 = tf32r(kr3), al3 = tf32r(kr3 - ah3);
#pragma unroll
            for (int j2 = 0; j2 < 2; j2++) {
                int q = qb + j2 * 8 + gid;
                float q0 = smf[QT + (d0 + tig) * 36 + q];
                float q1 = smf[QT + (d0 + tig + 4) * 36 + q];
                float qh0 = tf32r(q0), ql0 = tf32r(q0 - qh0);
                float qh1 = tf32r(q1), ql1 = tf32r(q1 - qh1);
                mma8(sc[j2], ah0, ah1, ah2, ah3, qh0, qh1);
                mma8(sc[j2], ah0, ah1, ah2, ah3, ql0, ql1);
                mma8(sc[j2], al0, al1, al2, al3, qh0, qh1);
            }
        }
        __syncthreads();                  // done reading Kraw
        if (s + 1 < NSUB_) {              // prefetch K(s+1)
            int ln = l0 + SK_;
#pragma unroll
            for (int i = 0; i < 8; i++) {
                int idx = t + i * 256, row = idx >> 5, c4 = idx & 31;
                cpasync16(sb + (KRAW + row * 132 + 4 * c4) * 4,
                          &Kh[(size_t)(ln + row) * D_ + 4 * c4]);
            }
            CP_COMMIT();
        }

        // ---- exp (tf32-rounded) -> Es, denominators ----
#pragma unroll
        for (int j2 = 0; j2 < 2; j2++) {
            float e0 = tf32r(__expf(sc[j2][0]));
            float e1 = tf32r(__expf(sc[j2][1]));
            float e2 = tf32r(__expf(sc[j2][2]));
            float e3 = tf32r(__expf(sc[j2][3]));
            int q0 = qb + j2 * 8 + 2 * tig;
            smf[ES + q0 * 68 + kb + gid]           = e0;
            smf[ES + (q0 + 1) * 68 + kb + gid]     = e1;
            smf[ES + q0 * 68 + kb + gid + 8]       = e2;
            smf[ES + (q0 + 1) * 68 + kb + gid + 8] = e3;
            float s0 = e0 + e2, s1 = e1 + e3;
#pragma unroll
            for (int off = 4; off < 32; off <<= 1) {
                s0 += __shfl_xor_sync(0xffffffffu, s0, off);
                s1 += __shfl_xor_sync(0xffffffffu, s1, off);
            }
            if (lane < 4) {
                atomicAdd(&smf[DEN + q0], s0);
                atomicAdd(&smf[DEN + q0 + 1], s1);
            }
        }

        if (s == NSUB_ - 1) CP_WAIT0(); else CP_WAIT1();   // V(s) ready
        __syncthreads();

        // overwrite fresh V rows
        {
            int lo_ = l0 > P ? l0 : P;
            int hi_ = (l0 + SK_) < (P + M_) ? (l0 + SK_) : (P + M_);
            if (lo_ < hi_) {
                for (int idx = t; idx < (hi_ - lo_) * 32; idx += 256) {
                    int r = idx >> 5, c4 = idx & 31;
                    int gl = lo_ + r;
                    *(float4*)&smf[VRAW + (gl - l0) * 132 + 4 * c4] =
                        *(const float4*)&g_qkv[(gl - P) * QKV3_ + 2 * N_ + h * D_ + 4 * c4];
                }
                __syncthreads();
            }
        }

        // ---- PV: E (rounded) x V (hi/lo 2-pass) ----
#pragma unroll 2
        for (int ks = 0; ks < 8; ks++) {
            int l = ks * 8;
            float a0[4], a1[4];
            a0[0] = smf[ES + gid * 68 + l + tig];
            a0[1] = smf[ES + (gid + 8) * 68 + l + tig];
            a0[2] = smf[ES + gid * 68 + l + tig + 4];
            a0[3] = smf[ES + (gid + 8) * 68 + l + tig + 4];
            a1[0] = smf[ES + (16 + gid) * 68 + l + tig];
            a1[1] = smf[ES + (24 + gid) * 68 + l + tig];
            a1[2] = smf[ES + (16 + gid) * 68 + l + tig + 4];
            a1[3] = smf[ES + (24 + gid) * 68 + l + tig + 4];
#pragma unroll
            for (int nb = 0; nb < 2; nb++) {
                int d = w * 16 + nb * 8 + gid;
                float v0 = smf[VRAW + (l + tig) * 132 + d];
                float v1 = smf[VRAW + (l + tig + 4) * 132 + d];
                float bh0 = tf32r(v0), bl0 = tf32r(v0 - bh0);
                float bh1 = tf32r(v1), bl1 = tf32r(v1 - bh1);
                mma8(o[0][nb], a0[0], a0[1], a0[2], a0[3], bh0, bh1);
                mma8(o[0][nb], a0[0], a0[1], a0[2], a0[3], bl0, bl1);
                mma8(o[1][nb], a1[0], a1[1], a1[2], a1[3], bh0, bh1);
                mma8(o[1][nb], a1[0], a1[1], a1[2], a1[3], bl0, bl1);
            }
        }
        __syncthreads();                  // done reading Vraw/Es
    }

    // ---- epilogue: write partials ----
    const size_t base = (size_t)(h * NC_ + c) * M_ * D_;
#pragma unroll
    for (int mt = 0; mt < 2; mt++)
#pragma unroll
        for (int nb = 0; nb < 2; nb++) {
            int q0 = mt * 16 + gid, d0 = w * 16 + nb * 8 + 2 * tig;
            *(float2*)&g_num[base + (size_t)q0 * D_ + d0] =
                make_float2(o[mt][nb][0], o[mt][nb][1]);
            *(float2*)&g_num[base + (size_t)(q0 + 8) * D_ + d0] =
                make_float2(o[mt][nb][2], o[mt][nb][3]);
        }
    if (t < 32) g_den[(h * NC_ + c) * M_ + t] = smf[DEN + t];
}

// ---- kernel 4: reduce ----
__global__ void reduce_out(float* __restrict__ out) {
    int hm = blockIdx.x, h = hm >> 5, m = hm & 31;
    int d = threadIdx.x;
    float dsum = 0.f, nsum = 0.f;
#pragma unroll 8
    for (int c = 0; c < NC_; c++) dsum += g_den[(h * NC_ + c) * M_ + m];
#pragma unroll 8
    for (int c = 0; c < NC_; c++)
        nsum += g_num[((size_t)(h * NC_ + c) * M_ + m) * D_ + d];
    out[m * N_ + h * D_ + d] = nsum / dsum;
}

extern "C" void kernel_launch(void* const* d_in, const int* in_sizes, int n_in,
                              void* d_out, int out_size) {
    const float* X  = (const float*)d_in[0];
    const float* W  = (const float*)d_in[1];
    const float* cK = (const float*)d_in[2];
    const float* cV = (const float*)d_in[3];
    const int*   P  = (const int*)d_in[4];
    float* out = (float*)d_out;

    cudaFuncSetAttribute(attn_mma, cudaFuncAttributeMaxDynamicSharedMemorySize, SMEMB);

    rms_kernel<<<M_, 256>>>(X);
    zero_qkv<<<(M_ * QKV3_ + 255) / 256, 256>>>();
    qkv_gemm<<<dim3(QKV3_ / BN2_, KSPLIT2_), 256>>>(X, W);
    attn_mma<<<dim3(NC_, H_), 256, SMEMB>>>(cK, cV, P);
    reduce_out<<<H_ * M_, 128>>>(out);
}

// round 9
// speedup vs baseline: 2.0481x; 1.1422x over previous
#include <cuda_runtime.h>
#include <cstdint>

#define M_     32
#define N_     2048
#define D_     128
#define L_     32768
#define H_     16
#define QKV3_  6144
#define CHUNK_ 1024
#define NC_    32
#define SK_    64          // keys per subtile
#define NSUB_  16          // CHUNK_/SK_

typedef unsigned long long u64;
typedef unsigned int u32;

__device__ float g_scale[M_];
__device__ float g_qkv[M_ * QKV3_];
__device__ float g_num[H_ * NC_ * M_ * D_];   // [hc][q][d]
__device__ float g_den[H_ * NC_ * M_];

// ---- helpers ----
__device__ __forceinline__ u64 ffma2(u64 a, u64 b, u64 c) {
    u64 d; asm("fma.rn.f32x2 %0, %1, %2, %3;" : "=l"(d) : "l"(a), "l"(b), "l"(c)); return d;
}
__device__ __forceinline__ u64 pack2(float lo, float hi) {
    u64 r; asm("mov.b64 %0, {%1, %2};" : "=l"(r) : "f"(lo), "f"(hi)); return r;
}
__device__ __forceinline__ u64 dup2(float x) { return pack2(x, x); }
__device__ __forceinline__ void unpack2(u64 v, float& lo, float& hi) {
    asm("mov.b64 {%0, %1}, %2;" : "=f"(lo), "=f"(hi) : "l"(v));
}
// tf32 "hi" part via bit-mask (exactly tf32-representable; 1-cyc LOP3 vs ~20-cyc cvt)
__device__ __forceinline__ float mh(float x) {
    return __uint_as_float(__float_as_uint(x) & 0xFFFFE000u);
}
__device__ __forceinline__ u32 cvta_smem(const void* p) {
    u32 a; asm("{ .reg .u64 t; cvta.to.shared.u64 t, %1; cvt.u32.u64 %0, t; }" : "=r"(a) : "l"(p)); return a;
}
__device__ __forceinline__ void cpasync16(u32 s, const void* g) {
    asm volatile("cp.async.cg.shared.global [%0], [%1], 16;" :: "r"(s), "l"(g));
}
#define CP_COMMIT() asm volatile("cp.async.commit_group;" ::: "memory")
#define CP_WAIT0()  asm volatile("cp.async.wait_group 0;" ::: "memory")
#define CP_WAIT1()  asm volatile("cp.async.wait_group 1;" ::: "memory")

// mma.sync m16n8k8 tf32 (legacy HMMA path, base ISA)
__device__ __forceinline__ void mma8(float* c, float a0, float a1, float a2, float a3,
                                     float b0, float b1) {
    asm volatile("mma.sync.aligned.m16n8k8.row.col.f32.tf32.tf32.f32 "
        "{%0,%1,%2,%3}, {%4,%5,%6,%7}, {%8,%9}, {%0,%1,%2,%3};"
        : "+f"(c[0]), "+f"(c[1]), "+f"(c[2]), "+f"(c[3])
        : "r"(__float_as_uint(a0)), "r"(__float_as_uint(a1)),
          "r"(__float_as_uint(a2)), "r"(__float_as_uint(a3)),
          "r"(__float_as_uint(b0)), "r"(__float_as_uint(b1)));
}

// ---- kernel 1: RMS scales ----
__global__ void rms_kernel(const float* __restrict__ X) {
    int m = blockIdx.x;
    float s = 0.f;
    for (int k = threadIdx.x; k < N_; k += 256) { float v = X[m * N_ + k]; s += v * v; }
    __shared__ float red[256];
    red[threadIdx.x] = s; __syncthreads();
    for (int o = 128; o > 0; o >>= 1) {
        if (threadIdx.x < o) red[threadIdx.x] += red[threadIdx.x + o];
        __syncthreads();
    }
    if (threadIdx.x == 0) g_scale[m] = rsqrtf(red[0] * (1.0f / N_));
}

__global__ void zero_qkv() {
    int i = blockIdx.x * 256 + threadIdx.x;
    if (i < M_ * QKV3_) g_qkv[i] = 0.f;
}

// ---- kernel 2: QKV GEMM (scalar f32x2, 8m x 2n) ----
#define BN2_     128
#define KC2_     32
#define KSPLIT2_ 8
#define KSLAB2_  (N_ / KSPLIT2_)
#define XS_S     36
__global__ __launch_bounds__(256) void qkv_gemm(const float* __restrict__ X,
                                                const float* __restrict__ W) {
    __shared__ float Xs[KC2_ * XS_S];
    __shared__ float Ws[KC2_ * BN2_];
    const int t = threadIdx.x, mg = t >> 6, ng = t & 63;
    const int colBase = blockIdx.x * BN2_, kBase0 = blockIdx.y * KSLAB2_;
    u64 acc[4][2];
#pragma unroll
    for (int i = 0; i < 4; i++) { acc[i][0] = 0ull; acc[i][1] = 0ull; }
    for (int kc = 0; kc < KSLAB2_; kc += KC2_) {
        const int kb = kBase0 + kc;
        __syncthreads();
#pragma unroll
        for (int i = 0; i < 4; i++) {
            int idx = t + i * 256, m = idx >> 5, kk = idx & 31;
            Xs[kk * XS_S + m] = X[m * N_ + kb + kk] * g_scale[m];
        }
#pragma unroll
        for (int i = 0; i < 4; i++) {
            int idx = t + i * 256, kk = idx >> 5, c4 = idx & 31;
            *(float4*)&Ws[kk * BN2_ + 4 * c4] =
                *(const float4*)&W[(size_t)(kb + kk) * QKV3_ + colBase + 4 * c4];
        }
        __syncthreads();
#pragma unroll 4
        for (int kk = 0; kk < KC2_; kk++) {
            float4 xa = *(const float4*)&Xs[kk * XS_S + mg * 8];
            float4 xb = *(const float4*)&Xs[kk * XS_S + mg * 8 + 4];
            u64 x01 = pack2(xa.x, xa.y), x23 = pack2(xa.z, xa.w);
            u64 x45 = pack2(xb.x, xb.y), x67 = pack2(xb.z, xb.w);
            u64 wv = *(const u64*)&Ws[kk * BN2_ + 2 * ng];
            float w0, w1; unpack2(wv, w0, w1);
            u64 wd0 = dup2(w0), wd1 = dup2(w1);
            acc[0][0] = ffma2(x01, wd0, acc[0][0]); acc[1][0] = ffma2(x23, wd0, acc[1][0]);
            acc[2][0] = ffma2(x45, wd0, acc[2][0]); acc[3][0] = ffma2(x67, wd0, acc[3][0]);
            acc[0][1] = ffma2(x01, wd1, acc[0][1]); acc[1][1] = ffma2(x23, wd1, acc[1][1]);
            acc[2][1] = ffma2(x45, wd1, acc[2][1]); acc[3][1] = ffma2(x67, wd1, acc[3][1]);
        }
    }
#pragma unroll
    for (int i = 0; i < 4; i++)
#pragma unroll
        for (int j = 0; j < 2; j++) {
            float a, b; unpack2(acc[i][j], a, b);
            int m0 = mg * 8 + 2 * i, col = colBase + 2 * ng + j;
            atomicAdd(&g_qkv[m0 * QKV3_ + col], a);
            atomicAdd(&g_qkv[(m0 + 1) * QKV3_ + col], b);
        }
}

// ---- kernel 3: mma.sync tf32 attention (mask-split, Q pre-split) ----
// smem float offsets
#define KRAW 0                         // [64][132]
#define VRAW 8448                      // [64][132]
#define QTH  16896                     // [128 d][36]  Q hi transposed
#define QTL  21504                     // [128 d][36]  Q lo transposed
#define ES   26112                     // [32 q][68]   rounded exp(scores)
#define DEN  28288                     // [32]
#define SMF  28320
#define SMEMB (SMF * 4)                // 113280 B

__global__ __launch_bounds__(256, 2) void attn_mma(
    const float* __restrict__ cK, const float* __restrict__ cV,
    const int* __restrict__ Pp)
{
    extern __shared__ float smf[];
    const u32 sb = cvta_smem(smf);
    const int t = threadIdx.x, w = t >> 5, lane = t & 31;
    const int gid = lane >> 2, tig = lane & 3;
    const int h = blockIdx.y, c = blockIdx.x, P = *Pp;
    const int kg = w >> 1, qh = w & 1;        // QK: key-group / query-half
    const int kb = kg * 16, qb = qh * 16;

    const float* Kh = cK + (size_t)h * L_ * D_;
    const float* Vh = cV + (size_t)h * L_ * D_;

    // stage Q transposed, pre-split hi/lo
#pragma unroll
    for (int i = 0; i < 16; i++) {
        int idx = t + i * 256;           // 0..4095
        int q = idx >> 7, d = idx & 127;
        float x = g_qkv[q * QKV3_ + h * D_ + d];
        float hi = mh(x);
        smf[QTH + d * 36 + q] = hi;
        smf[QTL + d * 36 + q] = x - hi;
    }
    if (t < 32) smf[DEN + t] = 0.f;

    float o[2][2][4];                     // PV accumulators [mtile][nblk][frag]
#pragma unroll
    for (int a = 0; a < 2; a++)
#pragma unroll
        for (int b = 0; b < 2; b++)
#pragma unroll
            for (int k = 0; k < 4; k++) o[a][b][k] = 0.f;

    // prologue: async-stage K(0)
    {
        int l0 = c * CHUNK_;
#pragma unroll
        for (int i = 0; i < 8; i++) {
            int idx = t + i * 256, row = idx >> 5, c4 = idx & 31;
            cpasync16(sb + (KRAW + row * 132 + 4 * c4) * 4,
                      &Kh[(size_t)(l0 + row) * D_ + 4 * c4]);
        }
        CP_COMMIT();
    }

    for (int s = 0; s < NSUB_; s++) {
        const int l0 = c * CHUNK_ + s * SK_;
        // stage V(s) async
#pragma unroll
        for (int i = 0; i < 8; i++) {
            int idx = t + i * 256, row = idx >> 5, c4 = idx & 31;
            cpasync16(sb + (VRAW + row * 132 + 4 * c4) * 4,
                      &Vh[(size_t)(l0 + row) * D_ + 4 * c4]);
        }
        CP_COMMIT();
        CP_WAIT1();                       // K(s) ready
        __syncthreads();

        // overwrite fresh K rows
        {
            int lo_ = l0 > P ? l0 : P;
            int hi_ = (l0 + SK_) < (P + M_) ? (l0 + SK_) : (P + M_);
            if (lo_ < hi_) {
                for (int idx = t; idx < (hi_ - lo_) * 32; idx += 256) {
                    int r = idx >> 5, c4 = idx & 31;
                    int gl = lo_ + r;
                    *(float4*)&smf[KRAW + (gl - l0) * 132 + 4 * c4] =
                        *(const float4*)&g_qkv[(gl - P) * QKV3_ + N_ + h * D_ + 4 * c4];
                }
                __syncthreads();
            }
        }

        // ---- QK scores: 3-pass hi/lo tf32 (mask split) ----
        float sc[2][4];
#pragma unroll
        for (int j = 0; j < 2; j++)
#pragma unroll
            for (int k = 0; k < 4; k++) sc[j][k] = 0.f;
#pragma unroll 4
        for (int ks = 0; ks < 16; ks++) {
            int d0 = ks * 8;
            float kr0 = smf[KRAW + (kb + gid) * 132 + d0 + tig];
            float kr1 = smf[KRAW + (kb + gid + 8) * 132 + d0 + tig];
            float kr2 = smf[KRAW + (kb + gid) * 132 + d0 + tig + 4];
            float kr3 = smf[KRAW + (kb + gid + 8) * 132 + d0 + tig + 4];
            float ah0 = mh(kr0), al0 = kr0 - ah0;
            float ah1 = mh(kr1), al1 = kr1 - ah1;
            float ah2 = mh(kr2), al2 = kr2 - ah2;
            float ah3 = mh(kr3), al3 = kr3 - ah3;
#pragma unroll
            for (int j2 = 0; j2 < 2; j2++) {
                int q = qb + j2 * 8 + gid;
                float qh0 = smf[QTH + (d0 + tig) * 36 + q];
                float ql0 = smf[QTL + (d0 + tig) * 36 + q];
                float qh1 = smf[QTH + (d0 + tig + 4) * 36 + q];
                float ql1 = smf[QTL + (d0 + tig + 4) * 36 + q];
                mma8(sc[j2], ah0, ah1, ah2, ah3, qh0, qh1);
                mma8(sc[j2], ah0, ah1, ah2, ah3, ql0, ql1);
                mma8(sc[j2], al0, al1, al2, al3, qh0, qh1);
            }
        }
        __syncthreads();                  // done reading Kraw
        if (s + 1 < NSUB_) {              // prefetch K(s+1)
            int ln = l0 + SK_;
#pragma unroll
            for (int i = 0; i < 8; i++) {
                int idx = t + i * 256, row = idx >> 5, c4 = idx & 31;
                cpasync16(sb + (KRAW + row * 132 + 4 * c4) * 4,
                          &Kh[(size_t)(ln + row) * D_ + 4 * c4]);
            }
            CP_COMMIT();
        }

        // ---- exp (tf32-mask-rounded) -> Es, denominators ----
#pragma unroll
        for (int j2 = 0; j2 < 2; j2++) {
            float e0 = mh(__expf(sc[j2][0]));
            float e1 = mh(__expf(sc[j2][1]));
            float e2 = mh(__expf(sc[j2][2]));
            float e3 = mh(__expf(sc[j2][3]));
            int q0 = qb + j2 * 8 + 2 * tig;
            smf[ES + q0 * 68 + kb + gid]           = e0;
            smf[ES + (q0 + 1) * 68 + kb + gid]     = e1;
            smf[ES + q0 * 68 + kb + gid + 8]       = e2;
            smf[ES + (q0 + 1) * 68 + kb + gid + 8] = e3;
            float s0 = e0 + e2, s1 = e1 + e3;
#pragma unroll
            for (int off = 4; off < 32; off <<= 1) {
                s0 += __shfl_xor_sync(0xffffffffu, s0, off);
                s1 += __shfl_xor_sync(0xffffffffu, s1, off);
            }
            if (lane < 4) {
                atomicAdd(&smf[DEN + q0], s0);
                atomicAdd(&smf[DEN + q0 + 1], s1);
            }
        }

        if (s == NSUB_ - 1) CP_WAIT0(); else CP_WAIT1();   // V(s) ready
        __syncthreads();

        // overwrite fresh V rows
        {
            int lo_ = l0 > P ? l0 : P;
            int hi_ = (l0 + SK_) < (P + M_) ? (l0 + SK_) : (P + M_);
            if (lo_ < hi_) {
                for (int idx = t; idx < (hi_ - lo_) * 32; idx += 256) {
                    int r = idx >> 5, c4 = idx & 31;
                    int gl = lo_ + r;
                    *(float4*)&smf[VRAW + (gl - l0) * 132 + 4 * c4] =
                        *(const float4*)&g_qkv[(gl - P) * QKV3_ + 2 * N_ + h * D_ + 4 * c4];
                }
                __syncthreads();
            }
        }

        // ---- PV: E (rounded) x V (hi/lo mask 2-pass) ----
#pragma unroll 2
        for (int ks = 0; ks < 8; ks++) {
            int l = ks * 8;
            float a0[4], a1[4];
            a0[0] = smf[ES + gid * 68 + l + tig];
            a0[1] = smf[ES + (gid + 8) * 68 + l + tig];
            a0[2] = smf[ES + gid * 68 + l + tig + 4];
            a0[3] = smf[ES + (gid + 8) * 68 + l + tig + 4];
            a1[0] = smf[ES + (16 + gid) * 68 + l + tig];
            a1[1] = smf[ES + (24 + gid) * 68 + l + tig];
            a1[2] = smf[ES + (16 + gid) * 68 + l + tig + 4];
            a1[3] = smf[ES + (24 + gid) * 68 + l + tig + 4];
#pragma unroll
            for (int nb = 0; nb < 2; nb++) {
                int d = w * 16 + nb * 8 + gid;
                float v0 = smf[VRAW + (l + tig) * 132 + d];
                float v1 = smf[VRAW + (l + tig + 4) * 132 + d];
                float bh0 = mh(v0), bl0 = v0 - bh0;
                float bh1 = mh(v1), bl1 = v1 - bh1;
                mma8(o[0][nb], a0[0], a0[1], a0[2], a0[3], bh0, bh1);
                mma8(o[0][nb], a0[0], a0[1], a0[2], a0[3], bl0, bl1);
                mma8(o[1][nb], a1[0], a1[1], a1[2], a1[3], bh0, bh1);
                mma8(o[1][nb], a1[0], a1[1], a1[2], a1[3], bl0, bl1);
            }
        }
        __syncthreads();                  // done reading Vraw/Es
    }

    // ---- epilogue: write partials ----
    const size_t base = (size_t)(h * NC_ + c) * M_ * D_;
#pragma unroll
    for (int mt = 0; mt < 2; mt++)
#pragma unroll
        for (int nb = 0; nb < 2; nb++) {
            int q0 = mt * 16 + gid, d0 = w * 16 + nb * 8 + 2 * tig;
            *(float2*)&g_num[base + (size_t)q0 * D_ + d0] =
                make_float2(o[mt][nb][0], o[mt][nb][1]);
            *(float2*)&g_num[base + (size_t)(q0 + 8) * D_ + d0] =
                make_float2(o[mt][nb][2], o[mt][nb][3]);
        }
    if (t < 32) g_den[(h * NC_ + c) * M_ + t] = smf[DEN + t];
}

// ---- kernel 4: reduce ----
__global__ void reduce_out(float* __restrict__ out) {
    int hm = blockIdx.x, h = hm >> 5, m = hm & 31;
    int d = threadIdx.x;
    float dsum = 0.f, nsum = 0.f;
#pragma unroll 8
    for (int c = 0; c < NC_; c++) dsum += g_den[(h * NC_ + c) * M_ + m];
#pragma unroll 8
    for (int c = 0; c < NC_; c++)
        nsum += g_num[((size_t)(h * NC_ + c) * M_ + m) * D_ + d];
    out[m * N_ + h * D_ + d] = nsum / dsum;
}

extern "C" void kernel_launch(void* const* d_in, const int* in_sizes, int n_in,
                              void* d_out, int out_size) {
    const float* X  = (const float*)d_in[0];
    const float* W  = (const float*)d_in[1];
    const float* cK = (const float*)d_in[2];
    const float* cV = (const float*)d_in[3];
    const int*   P  = (const int*)d_in[4];
    float* out = (float*)d_out;

    cudaFuncSetAttribute(attn_mma, cudaFuncAttributeMaxDynamicSharedMemorySize, SMEMB);

    rms_kernel<<<M_, 256>>>(X);
    zero_qkv<<<(M_ * QKV3_ + 255) / 256, 256>>>();
    qkv_gemm<<<dim3(QKV3_ / BN2_, KSPLIT2_), 256>>>(X, W);
    attn_mma<<<dim3(NC_, H_), 256, SMEMB>>>(cK, cV, P);
    reduce_out<<<H_ * M_, 128>>>(out);
}

// round 10
// speedup vs baseline: 2.0718x; 1.0116x over previous
#include <cuda_runtime.h>
#include <cstdint>

#define M_     32
#define N_     2048
#define D_     128
#define L_     32768
#define H_     16
#define QKV3_  6144
#define CHUNK_ 1024
#define NC_    32
#define SK_    64          // keys per subtile
#define NSUB_  16          // CHUNK_/SK_

typedef unsigned long long u64;
typedef unsigned int u32;

__device__ float g_scale[M_];
__device__ float g_qkv[M_ * QKV3_];
__device__ float g_num[H_ * NC_ * M_ * D_];   // [hc][q][d]
__device__ float g_den[H_ * NC_ * M_];

// ---- helpers ----
__device__ __forceinline__ u64 ffma2(u64 a, u64 b, u64 c) {
    u64 d; asm("fma.rn.f32x2 %0, %1, %2, %3;" : "=l"(d) : "l"(a), "l"(b), "l"(c)); return d;
}
__device__ __forceinline__ u64 pack2(float lo, float hi) {
    u64 r; asm("mov.b64 %0, {%1, %2};" : "=l"(r) : "f"(lo), "f"(hi)); return r;
}
__device__ __forceinline__ u64 dup2(float x) { return pack2(x, x); }
__device__ __forceinline__ void unpack2(u64 v, float& lo, float& hi) {
    asm("mov.b64 {%0, %1}, %2;" : "=f"(lo), "=f"(hi) : "l"(v));
}
// tf32 "hi" mask (13-bit mantissa) — used by PV path
__device__ __forceinline__ float mh(float x) {
    return __uint_as_float(__float_as_uint(x) & 0xFFFFE000u);
}
// bf16 "hi" mask (truncation, exactly bf16-representable)
__device__ __forceinline__ float bh(float x) {
    return __uint_as_float(__float_as_uint(x) & 0xFFFF0000u);
}
// pack two floats' bf16 truncations: {lo16=a, hi16=b}
__device__ __forceinline__ u32 bpack(float a, float b) {
    u32 r;
    asm("prmt.b32 %0, %1, %2, 0x7632;" : "=r"(r)
        : "r"(__float_as_uint(a)), "r"(__float_as_uint(b)));
    return r;
}
__device__ __forceinline__ u32 cvta_smem(const void* p) {
    u32 a; asm("{ .reg .u64 t; cvta.to.shared.u64 t, %1; cvt.u32.u64 %0, t; }" : "=r"(a) : "l"(p)); return a;
}
__device__ __forceinline__ void cpasync16(u32 s, const void* g) {
    asm volatile("cp.async.cg.shared.global [%0], [%1], 16;" :: "r"(s), "l"(g));
}
#define CP_COMMIT() asm volatile("cp.async.commit_group;" ::: "memory")
#define CP_WAIT0()  asm volatile("cp.async.wait_group 0;" ::: "memory")

__device__ __forceinline__ void ldsm4(u32& r0, u32& r1, u32& r2, u32& r3, u32 a) {
    asm volatile("ldmatrix.sync.aligned.m8n8.x4.shared.b16 {%0,%1,%2,%3}, [%4];"
        : "=r"(r0), "=r"(r1), "=r"(r2), "=r"(r3) : "r"(a));
}
__device__ __forceinline__ void ldsm2(u32& r0, u32& r1, u32 a) {
    asm volatile("ldmatrix.sync.aligned.m8n8.x2.shared.b16 {%0,%1}, [%2];"
        : "=r"(r0), "=r"(r1) : "r"(a));
}
// bf16 m16n8k16
__device__ __forceinline__ void mma16(float* c, u32 a0, u32 a1, u32 a2, u32 a3,
                                      u32 b0, u32 b1) {
    asm volatile("mma.sync.aligned.m16n8k16.row.col.f32.bf16.bf16.f32 "
        "{%0,%1,%2,%3}, {%4,%5,%6,%7}, {%8,%9}, {%0,%1,%2,%3};"
        : "+f"(c[0]), "+f"(c[1]), "+f"(c[2]), "+f"(c[3])
        : "r"(a0), "r"(a1), "r"(a2), "r"(a3), "r"(b0), "r"(b1));
}
// tf32 m16n8k8
__device__ __forceinline__ void mma8(float* c, float a0, float a1, float a2, float a3,
                                     float b0, float b1) {
    asm volatile("mma.sync.aligned.m16n8k8.row.col.f32.tf32.tf32.f32 "
        "{%0,%1,%2,%3}, {%4,%5,%6,%7}, {%8,%9}, {%0,%1,%2,%3};"
        : "+f"(c[0]), "+f"(c[1]), "+f"(c[2]), "+f"(c[3])
        : "r"(__float_as_uint(a0)), "r"(__float_as_uint(a1)),
          "r"(__float_as_uint(a2)), "r"(__float_as_uint(a3)),
          "r"(__float_as_uint(b0)), "r"(__float_as_uint(b1)));
}

// ---- kernel 1: RMS scales ----
__global__ void rms_kernel(const float* __restrict__ X) {
    int m = blockIdx.x;
    float s = 0.f;
    for (int k = threadIdx.x; k < N_; k += 256) { float v = X[m * N_ + k]; s += v * v; }
    __shared__ float red[256];
    red[threadIdx.x] = s; __syncthreads();
    for (int o = 128; o > 0; o >>= 1) {
        if (threadIdx.x < o) red[threadIdx.x] += red[threadIdx.x + o];
        __syncthreads();
    }
    if (threadIdx.x == 0) g_scale[m] = rsqrtf(red[0] * (1.0f / N_));
}

__global__ void zero_qkv() {
    int i = blockIdx.x * 256 + threadIdx.x;
    if (i < M_ * QKV3_) g_qkv[i] = 0.f;
}

// ---- kernel 2: QKV GEMM (scalar f32x2, 8m x 2n) ----
#define BN2_     128
#define KC2_     32
#define KSPLIT2_ 8
#define KSLAB2_  (N_ / KSPLIT2_)
#define XS_S     36
__global__ __launch_bounds__(256) void qkv_gemm(const float* __restrict__ X,
                                                const float* __restrict__ W) {
    __shared__ float Xs[KC2_ * XS_S];
    __shared__ float Ws[KC2_ * BN2_];
    const int t = threadIdx.x, mg = t >> 6, ng = t & 63;
    const int colBase = blockIdx.x * BN2_, kBase0 = blockIdx.y * KSLAB2_;
    u64 acc[4][2];
#pragma unroll
    for (int i = 0; i < 4; i++) { acc[i][0] = 0ull; acc[i][1] = 0ull; }
    for (int kc = 0; kc < KSLAB2_; kc += KC2_) {
        const int kb = kBase0 + kc;
        __syncthreads();
#pragma unroll
        for (int i = 0; i < 4; i++) {
            int idx = t + i * 256, m = idx >> 5, kk = idx & 31;
            Xs[kk * XS_S + m] = X[m * N_ + kb + kk] * g_scale[m];
        }
#pragma unroll
        for (int i = 0; i < 4; i++) {
            int idx = t + i * 256, kk = idx >> 5, c4 = idx & 31;
            *(float4*)&Ws[kk * BN2_ + 4 * c4] =
                *(const float4*)&W[(size_t)(kb + kk) * QKV3_ + colBase + 4 * c4];
        }
        __syncthreads();
#pragma unroll 4
        for (int kk = 0; kk < KC2_; kk++) {
            float4 xa = *(const float4*)&Xs[kk * XS_S + mg * 8];
            float4 xb = *(const float4*)&Xs[kk * XS_S + mg * 8 + 4];
            u64 x01 = pack2(xa.x, xa.y), x23 = pack2(xa.z, xa.w);
            u64 x45 = pack2(xb.x, xb.y), x67 = pack2(xb.z, xb.w);
            u64 wv = *(const u64*)&Ws[kk * BN2_ + 2 * ng];
            float w0, w1; unpack2(wv, w0, w1);
            u64 wd0 = dup2(w0), wd1 = dup2(w1);
            acc[0][0] = ffma2(x01, wd0, acc[0][0]); acc[1][0] = ffma2(x23, wd0, acc[1][0]);
            acc[2][0] = ffma2(x45, wd0, acc[2][0]); acc[3][0] = ffma2(x67, wd0, acc[3][0]);
            acc[0][1] = ffma2(x01, wd1, acc[0][1]); acc[1][1] = ffma2(x23, wd1, acc[1][1]);
            acc[2][1] = ffma2(x45, wd1, acc[2][1]); acc[3][1] = ffma2(x67, wd1, acc[3][1]);
        }
    }
#pragma unroll
    for (int i = 0; i < 4; i++)
#pragma unroll
        for (int j = 0; j < 2; j++) {
            float a, b; unpack2(acc[i][j], a, b);
            int m0 = mg * 8 + 2 * i, col = colBase + 2 * ng + j;
            atomicAdd(&g_qkv[m0 * QKV3_ + col], a);
            atomicAdd(&g_qkv[(m0 + 1) * QKV3_ + col], b);
        }
}

// ---- kernel 3: attention: bf16 QK (ldmatrix) + tf32 PV ----
// smem map (bytes):
//   0      KSTG fp32 [64][132]     33792   (K then V staging, shared)
//   33792  KHI  bf16 [64][256B]    16384   (swizzled 16B chunks)
//   50176  KLO  bf16 [64][256B]    16384
//   66560  QHI  bf16 [32][256B]     8192
//   74752  QLO  bf16 [32][256B]     8192
//   82944  ES   fp32 [32][68]       8704
//   91648  DEN  fp32 [32]            128
#define KHI_B  33792
#define KLO_B  50176
#define QHI_B  66560
#define QLO_B  74752
#define ES_F   20736
#define DEN_F  22912
#define SMEMB  91776

__global__ __launch_bounds__(256, 2) void attn_mma(
    const float* __restrict__ cK, const float* __restrict__ cV,
    const int* __restrict__ Pp)
{
    extern __shared__ float smf[];
    char* smb = (char*)smf;
    const u32 sb = cvta_smem(smf);
    const int t = threadIdx.x, w = t >> 5, lane = t & 31;
    const int gid = lane >> 2, tig = lane & 3;
    const int h = blockIdx.y, c = blockIdx.x, P = *Pp;
    const int kg = w >> 1, qh = w & 1;
    const int kb = kg * 16, qb = qh * 16;

    const float* Kh = cK + (size_t)h * L_ * D_;
    const float* Vh = cV + (size_t)h * L_ * D_;

    // ---- stage Q bf16 hi/lo (swizzled) ----
    {
        int q = t >> 3, c2 = t & 7;
#pragma unroll
        for (int i = 0; i < 2; i++) {
            int ch = 2 * c2 + i;
            const float* src = &g_qkv[q * QKV3_ + h * D_ + 8 * ch];
            float4 x = *(const float4*)src;
            float4 y = *(const float4*)(src + 4);
            u32 sw = (u32)(q * 256 + ((ch ^ (q & 7)) << 4));
            *(uint4*)(smb + QHI_B + sw) =
                make_uint4(bpack(x.x, x.y), bpack(x.z, x.w), bpack(y.x, y.y), bpack(y.z, y.w));
            float l0 = x.x - bh(x.x), l1 = x.y - bh(x.y), l2 = x.z - bh(x.z), l3 = x.w - bh(x.w);
            float l4 = y.x - bh(y.x), l5 = y.y - bh(y.y), l6 = y.z - bh(y.z), l7 = y.w - bh(y.w);
            *(uint4*)(smb + QLO_B + sw) =
                make_uint4(bpack(l0, l1), bpack(l2, l3), bpack(l4, l5), bpack(l6, l7));
        }
    }
    if (t < 32) smf[DEN_F + t] = 0.f;

    float o[2][2][4];
#pragma unroll
    for (int a = 0; a < 2; a++)
#pragma unroll
        for (int b = 0; b < 2; b++)
#pragma unroll
            for (int k = 0; k < 4; k++) o[a][b][k] = 0.f;

    // ldmatrix per-lane address bases
    const int subm = lane >> 3;                       // 0..3
    const int rowA = kb + (lane & 7) + ((subm & 1) << 3);
    const int chA  = subm >> 1;                       // 0/1: second k8 half
    const int rowB0 = qb + (lane & 7);                // + j2*8
    const int chB  = (lane >> 3) & 1;

    // prologue: stage K(0)
    {
        int l0 = c * CHUNK_;
#pragma unroll
        for (int i = 0; i < 8; i++) {
            int idx = t + i * 256, row = idx >> 5, c4 = idx & 31;
            cpasync16(sb + (row * 132 + 4 * c4) * 4, &Kh[(size_t)(l0 + row) * D_ + 4 * c4]);
        }
        CP_COMMIT();
    }

    for (int s = 0; s < NSUB_; s++) {
        const int l0 = c * CHUNK_ + s * SK_;
        CP_WAIT0();
        __syncthreads();                      // K(s) staged (and Q/ES ready)

        // fresh K rows
        {
            int lo_ = l0 > P ? l0 : P;
            int hi_ = (l0 + SK_) < (P + M_) ? (l0 + SK_) : (P + M_);
            if (lo_ < hi_) {
                for (int idx = t; idx < (hi_ - lo_) * 32; idx += 256) {
                    int r = idx >> 5, c4 = idx & 31;
                    int gl = lo_ + r;
                    *(float4*)&smf[(gl - l0) * 132 + 4 * c4] =
                        *(const float4*)&g_qkv[(gl - P) * QKV3_ + N_ + h * D_ + 4 * c4];
                }
                __syncthreads();
            }
        }

        // ---- convert K -> KHI/KLO bf16 (swizzled) ----
        {
            int row = t >> 2, c4 = t & 3;
            const float* src = smf + row * 132;
            char* hid = smb + KHI_B + row * 256;
            char* lod = smb + KLO_B + row * 256;
#pragma unroll
            for (int i = 0; i < 4; i++) {
                int ch = 4 * c4 + i;
                float4 x = *(const float4*)(src + 8 * ch);
                float4 y = *(const float4*)(src + 8 * ch + 4);
                u32 sw = (u32)((ch ^ (row & 7)) << 4);
                *(uint4*)(hid + sw) =
                    make_uint4(bpack(x.x, x.y), bpack(x.z, x.w), bpack(y.x, y.y), bpack(y.z, y.w));
                float l0f = x.x - bh(x.x), l1f = x.y - bh(x.y), l2f = x.z - bh(x.z), l3f = x.w - bh(x.w);
                float l4f = y.x - bh(y.x), l5f = y.y - bh(y.y), l6f = y.z - bh(y.z), l7f = y.w - bh(y.w);
                *(uint4*)(lod + sw) =
                    make_uint4(bpack(l0f, l1f), bpack(l2f, l3f), bpack(l4f, l5f), bpack(l6f, l7f));
            }
        }
        __syncthreads();                      // KB16 ready; KSTG free

        // stage V(s) into KSTG
#pragma unroll
        for (int i = 0; i < 8; i++) {
            int idx = t + i * 256, row = idx >> 5, c4 = idx & 31;
            cpasync16(sb + (row * 132 + 4 * c4) * 4, &Vh[(size_t)(l0 + row) * D_ + 4 * c4]);
        }
        CP_COMMIT();

        // ---- QK: bf16 3-pass, ldmatrix operands ----
        float sc[2][4];
#pragma unroll
        for (int j = 0; j < 2; j++)
#pragma unroll
            for (int k = 0; k < 4; k++) sc[j][k] = 0.f;
#pragma unroll
        for (int ks = 0; ks < 8; ks++) {
            u32 ka0, ka1, ka2, ka3, kl0, kl1, kl2, kl3;
            u32 swA = (u32)(rowA * 256 + (((2 * ks + chA) ^ (rowA & 7)) << 4));
            ldsm4(ka0, ka1, ka2, ka3, sb + KHI_B + swA);
            ldsm4(kl0, kl1, kl2, kl3, sb + KLO_B + swA);
#pragma unroll
            for (int j2 = 0; j2 < 2; j2++) {
                int rowB = rowB0 + j2 * 8;
                u32 swB = (u32)(rowB * 256 + (((2 * ks + chB) ^ (rowB & 7)) << 4));
                u32 qh0, qh1, ql0, ql1;
                ldsm2(qh0, qh1, sb + QHI_B + swB);
                ldsm2(ql0, ql1, sb + QLO_B + swB);
                mma16(sc[j2], ka0, ka1, ka2, ka3, qh0, qh1);
                mma16(sc[j2], kl0, kl1, kl2, kl3, qh0, qh1);
                mma16(sc[j2], ka0, ka1, ka2, ka3, ql0, ql1);
            }
        }

        // ---- exp (tf32-mask) -> ES, denominators ----
#pragma unroll
        for (int j2 = 0; j2 < 2; j2++) {
            float e0 = mh(__expf(sc[j2][0]));
            float e1 = mh(__expf(sc[j2][1]));
            float e2 = mh(__expf(sc[j2][2]));
            float e3 = mh(__expf(sc[j2][3]));
            int q0 = qb + j2 * 8 + 2 * tig;
            smf[ES_F + q0 * 68 + kb + gid]           = e0;
            smf[ES_F + (q0 + 1) * 68 + kb + gid]     = e1;
            smf[ES_F + q0 * 68 + kb + gid + 8]       = e2;
            smf[ES_F + (q0 + 1) * 68 + kb + gid + 8] = e3;
            float s0 = e0 + e2, s1 = e1 + e3;
#pragma unroll
            for (int off = 4; off < 32; off <<= 1) {
                s0 += __shfl_xor_sync(0xffffffffu, s0, off);
                s1 += __shfl_xor_sync(0xffffffffu, s1, off);
            }
            if (lane < 4) {
                atomicAdd(&smf[DEN_F + q0], s0);
                atomicAdd(&smf[DEN_F + q0 + 1], s1);
            }
        }

        CP_WAIT0();
        __syncthreads();                      // V staged + ES visible

        // fresh V rows
        {
            int lo_ = l0 > P ? l0 : P;
            int hi_ = (l0 + SK_) < (P + M_) ? (l0 + SK_) : (P + M_);
            if (lo_ < hi_) {
                for (int idx = t; idx < (hi_ - lo_) * 32; idx += 256) {
                    int r = idx >> 5, c4 = idx & 31;
                    int gl = lo_ + r;
                    *(float4*)&smf[(gl - l0) * 132 + 4 * c4] =
                        *(const float4*)&g_qkv[(gl - P) * QKV3_ + 2 * N_ + h * D_ + 4 * c4];
                }
                __syncthreads();
            }
        }

        // ---- PV: E (tf32-rounded) x V (hi/lo mask 2-pass, tf32) ----
#pragma unroll 2
        for (int ks = 0; ks < 8; ks++) {
            int l = ks * 8;
            float a0[4], a1[4];
            a0[0] = smf[ES_F + gid * 68 + l + tig];
            a0[1] = smf[ES_F + (gid + 8) * 68 + l + tig];
            a0[2] = smf[ES_F + gid * 68 + l + tig + 4];
            a0[3] = smf[ES_F + (gid + 8) * 68 + l + tig + 4];
            a1[0] = smf[ES_F + (16 + gid) * 68 + l + tig];
            a1[1] = smf[ES_F + (24 + gid) * 68 + l + tig];
            a1[2] = smf[ES_F + (16 + gid) * 68 + l + tig + 4];
            a1[3] = smf[ES_F + (24 + gid) * 68 + l + tig + 4];
#pragma unroll
            for (int nb = 0; nb < 2; nb++) {
                int d = w * 16 + nb * 8 + gid;
                float v0 = smf[(l + tig) * 132 + d];
                float v1 = smf[(l + tig + 4) * 132 + d];
                float bh0 = mh(v0), bl0 = v0 - bh0;
                float bh1 = mh(v1), bl1 = v1 - bh1;
                mma8(o[0][nb], a0[0], a0[1], a0[2], a0[3], bh0, bh1);
                mma8(o[0][nb], a0[0], a0[1], a0[2], a0[3], bl0, bl1);
                mma8(o[1][nb], a1[0], a1[1], a1[2], a1[3], bh0, bh1);
                mma8(o[1][nb], a1[0], a1[1], a1[2], a1[3], bl0, bl1);
            }
        }
        __syncthreads();                      // done reading KSTG/ES

        if (s + 1 < NSUB_) {                  // stage K(s+1)
            int ln = l0 + SK_;
#pragma unroll
            for (int i = 0; i < 8; i++) {
                int idx = t + i * 256, row = idx >> 5, c4 = idx & 31;
                cpasync16(sb + (row * 132 + 4 * c4) * 4, &Kh[(size_t)(ln + row) * D_ + 4 * c4]);
            }
            CP_COMMIT();
        }
    }

    // ---- epilogue ----
    const size_t base = (size_t)(h * NC_ + c) * M_ * D_;
#pragma unroll
    for (int mt = 0; mt < 2; mt++)
#pragma unroll
        for (int nb = 0; nb < 2; nb++) {
            int q0 = mt * 16 + gid, d0 = w * 16 + nb * 8 + 2 * tig;
            *(float2*)&g_num[base + (size_t)q0 * D_ + d0] =
                make_float2(o[mt][nb][0], o[mt][nb][1]);
            *(float2*)&g_num[base + (size_t)(q0 + 8) * D_ + d0] =
                make_float2(o[mt][nb][2], o[mt][nb][3]);
        }
    if (t < 32) g_den[(h * NC_ + c) * M_ + t] = smf[DEN_F + t];
}

// ---- kernel 4: reduce ----
__global__ void reduce_out(float* __restrict__ out) {
    int hm = blockIdx.x, h = hm >> 5, m = hm & 31;
    int d = threadIdx.x;
    float dsum = 0.f, nsum = 0.f;
#pragma unroll 8
    for (int c = 0; c < NC_; c++) dsum += g_den[(h * NC_ + c) * M_ + m];
#pragma unroll 8
    for (int c = 0; c < NC_; c++)
        nsum += g_num[((size_t)(h * NC_ + c) * M_ + m) * D_ + d];
    out[m * N_ + h * D_ + d] = nsum / dsum;
}

extern "C" void kernel_launch(void* const* d_in, const int* in_sizes, int n_in,
                              void* d_out, int out_size) {
    const float* X  = (const float*)d_in[0];
    const float* W  = (const float*)d_in[1];
    const float* cK = (const float*)d_in[2];
    const float* cV = (const float*)d_in[3];
    const int*   P  = (const int*)d_in[4];
    float* out = (float*)d_out;

    cudaFuncSetAttribute(attn_mma, cudaFuncAttributeMaxDynamicSharedMemorySize, SMEMB);

    rms_kernel<<<M_, 256>>>(X);
    zero_qkv<<<(M_ * QKV3_ + 255) / 256, 256>>>();
    qkv_gemm<<<dim3(QKV3_ / BN2_, KSPLIT2_), 256>>>(X, W);
    attn_mma<<<dim3(NC_, H_), 256, SMEMB>>>(cK, cV, P);
    reduce_out<<<H_ * M_, 128>>>(out);
}